// round 2
// baseline (speedup 1.0000x reference)
#include <cuda_runtime.h>
#include <cstdint>

// ============================================================================
// Induction capsule routing, algebraically restructured (sm_103-safe, no tcgen05)
//
//   e = x@W is never materialized:
//     c_i = (sum_s d_is x_is) @ W          (u = weighted x reduce; c = u@W)
//     b  += x · (W c)                      (v = c@W^T; b_cs = x_cs . v_c)
//   All fp32 -> numerics track the fp32 reference to ~1e-6.
// ============================================================================

static constexpr int C_CAPS = 64;
static constexpr int S_LEN  = 128;
static constexpr int H_DIM  = 2048;

// ---- scratch (device globals; allocation-free rule) ----
__device__ float g_b[C_CAPS * S_LEN];            // logits [64,128]
__device__ float g_u[C_CAPS * H_DIM];            // weighted x sums [64,2048]
__device__ float g_v[C_CAPS * H_DIM];            // W @ c per capsule [64,2048]
__device__ float g_Wt[(size_t)H_DIM * H_DIM];    // W transposed (16 MB)

// ============================================================================
// transpose: g_Wt[n][k] = W[k][n]
// ============================================================================
__global__ void transpose_kernel(const float* __restrict__ W) {
    __shared__ float t[32][33];
    int bx = blockIdx.x, by = blockIdx.y;
    int tx = threadIdx.x, ty = threadIdx.y;
    int col = bx * 32 + tx;
    #pragma unroll
    for (int j = 0; j < 32; j += 8)
        t[ty + j][tx] = W[(size_t)(by * 32 + ty + j) * H_DIM + col];
    __syncthreads();
    int ocol = by * 32 + tx;
    #pragma unroll
    for (int j = 0; j < 32; j += 8)
        g_Wt[(size_t)(bx * 32 + ty + j) * H_DIM + ocol] = t[tx][ty + j];
}

__global__ void zero_b_kernel() {
    int i = blockIdx.x * blockDim.x + threadIdx.x;
    if (i < C_CAPS * S_LEN) g_b[i] = 0.0f;
}

// ============================================================================
// u_kernel: d = softmax(b[cap,:]); u[cap,h] = sum_s d[s] * x[cap,s,h]
// grid (H/256, C), block 256
// ============================================================================
__global__ void __launch_bounds__(256) u_kernel(const float* __restrict__ x) {
    const int cap = blockIdx.y;
    const int tid = threadIdx.x;
    const int h = blockIdx.x * 256 + tid;
    __shared__ float d[S_LEN];

    if (tid < S_LEN) d[tid] = g_b[cap * S_LEN + tid];
    __syncthreads();
    if (tid < 32) {
        float x0 = d[tid], x1 = d[tid + 32], x2 = d[tid + 64], x3 = d[tid + 96];
        float mx = fmaxf(fmaxf(x0, x1), fmaxf(x2, x3));
        #pragma unroll
        for (int o = 16; o > 0; o >>= 1) mx = fmaxf(mx, __shfl_xor_sync(0xffffffffu, mx, o));
        float e0 = __expf(x0 - mx), e1 = __expf(x1 - mx);
        float e2 = __expf(x2 - mx), e3 = __expf(x3 - mx);
        float s = (e0 + e1) + (e2 + e3);
        #pragma unroll
        for (int o = 16; o > 0; o >>= 1) s += __shfl_xor_sync(0xffffffffu, s, o);
        float inv = 1.0f / s;
        d[tid] = e0 * inv; d[tid + 32] = e1 * inv; d[tid + 64] = e2 * inv; d[tid + 96] = e3 * inv;
    }
    __syncthreads();

    const float* xp = x + (size_t)cap * S_LEN * H_DIM + h;
    float a0 = 0.f, a1 = 0.f, a2 = 0.f, a3 = 0.f;
    #pragma unroll 8
    for (int s = 0; s < S_LEN; s += 4) {
        a0 = fmaf(d[s + 0], xp[(size_t)(s + 0) * H_DIM], a0);
        a1 = fmaf(d[s + 1], xp[(size_t)(s + 1) * H_DIM], a1);
        a2 = fmaf(d[s + 2], xp[(size_t)(s + 2) * H_DIM], a2);
        a3 = fmaf(d[s + 3], xp[(size_t)(s + 3) * H_DIM], a3);
    }
    g_u[cap * H_DIM + h] = (a0 + a1) + (a2 + a3);
}

// ============================================================================
// dot_gemm: Out[m][j] = sum_h A[m][h] * B[j][h]
//   A: [64, 2048] row-major, B: [2048, 2048] row-major, Out: [64, 2048]
//   grid 128 blocks (16 j-rows each), block 256 = 4 h-groups x 64 threads,
//   thread tile 4m x 4j, in-block deterministic h-split reduction.
// ============================================================================
__global__ void __launch_bounds__(256) dot_gemm_kernel(const float* __restrict__ A,
                                                       const float* __restrict__ B,
                                                       float* __restrict__ Out) {
    __shared__ float As[4][64][33];   // 33792 B
    __shared__ float Bs[4][16][33];   //  8448 B

    const int tid = threadIdx.x;
    const int g = tid >> 6;           // h-group 0..3  (h range g*512 .. +512)
    const int t = tid & 63;
    const int tm = t & 15;            // m-tile index
    const int tjj = t >> 4;           // j-tile index 0..3
    const int m0 = tm * 4;
    const int jj0 = tjj * 4;
    const int hbase = g * 512;
    const int j0 = blockIdx.x * 16;

    float acc[4][4] = {};

    for (int hc = 0; hc < 512; hc += 32) {
        // load A chunk [64 x 32] (coalesced float4, scalar smem stores)
        #pragma unroll
        for (int i = 0; i < 8; i++) {
            int idx = t + 64 * i;
            int m = idx >> 3, hv = idx & 7;
            float4 va = *(const float4*)(A + (size_t)m * H_DIM + hbase + hc + hv * 4);
            As[g][m][hv * 4 + 0] = va.x;
            As[g][m][hv * 4 + 1] = va.y;
            As[g][m][hv * 4 + 2] = va.z;
            As[g][m][hv * 4 + 3] = va.w;
        }
        // load B chunk [16 x 32]
        #pragma unroll
        for (int i = 0; i < 2; i++) {
            int idx = t + 64 * i;
            int j = idx >> 3, hv = idx & 7;
            float4 vb = *(const float4*)(B + (size_t)(j0 + j) * H_DIM + hbase + hc + hv * 4);
            Bs[g][j][hv * 4 + 0] = vb.x;
            Bs[g][j][hv * 4 + 1] = vb.y;
            Bs[g][j][hv * 4 + 2] = vb.z;
            Bs[g][j][hv * 4 + 3] = vb.w;
        }
        __syncthreads();
        #pragma unroll
        for (int hh = 0; hh < 32; hh++) {
            float a0 = As[g][m0 + 0][hh];
            float a1 = As[g][m0 + 1][hh];
            float a2 = As[g][m0 + 2][hh];
            float a3 = As[g][m0 + 3][hh];
            float b0 = Bs[g][jj0 + 0][hh];
            float b1 = Bs[g][jj0 + 1][hh];
            float b2 = Bs[g][jj0 + 2][hh];
            float b3 = Bs[g][jj0 + 3][hh];
            acc[0][0] = fmaf(a0, b0, acc[0][0]); acc[0][1] = fmaf(a0, b1, acc[0][1]);
            acc[0][2] = fmaf(a0, b2, acc[0][2]); acc[0][3] = fmaf(a0, b3, acc[0][3]);
            acc[1][0] = fmaf(a1, b0, acc[1][0]); acc[1][1] = fmaf(a1, b1, acc[1][1]);
            acc[1][2] = fmaf(a1, b2, acc[1][2]); acc[1][3] = fmaf(a1, b3, acc[1][3]);
            acc[2][0] = fmaf(a2, b0, acc[2][0]); acc[2][1] = fmaf(a2, b1, acc[2][1]);
            acc[2][2] = fmaf(a2, b2, acc[2][2]); acc[2][3] = fmaf(a2, b3, acc[2][3]);
            acc[3][0] = fmaf(a3, b0, acc[3][0]); acc[3][1] = fmaf(a3, b1, acc[3][1]);
            acc[3][2] = fmaf(a3, b2, acc[3][2]); acc[3][3] = fmaf(a3, b3, acc[3][3]);
        }
        __syncthreads();
    }

    // deterministic cross-group reduction (reuse As as partial buffer: 4096 floats)
    float* pr = &As[0][0][0];
    #pragma unroll
    for (int i = 0; i < 4; i++)
        #pragma unroll
        for (int k = 0; k < 4; k++)
            pr[g * 1024 + (m0 + i) * 16 + jj0 + k] = acc[i][k];
    __syncthreads();
    for (int o = tid; o < 1024; o += 256) {
        float s = (pr[o] + pr[1024 + o]) + (pr[2048 + o] + pr[3072 + o]);
        int m = o >> 4, jl = o & 15;
        Out[(size_t)m * H_DIM + j0 + jl] = s;
    }
}

// ============================================================================
// squash: c *= s/(1+s)/sqrt(s+1e-9), s = ||c_row||^2   (block per capsule)
// ============================================================================
__global__ void __launch_bounds__(256) squash_kernel(float* __restrict__ cbuf) {
    const int cap = blockIdx.x;
    const int tid = threadIdx.x;
    float* row = cbuf + cap * H_DIM;
    float v[8]; float s = 0.f;
    #pragma unroll
    for (int j = 0; j < 8; j++) { v[j] = row[tid + 256 * j]; s = fmaf(v[j], v[j], s); }
    #pragma unroll
    for (int o = 16; o > 0; o >>= 1) s += __shfl_xor_sync(0xffffffffu, s, o);
    __shared__ float rs[8];
    __shared__ float coeff_s;
    if ((tid & 31) == 0) rs[tid >> 5] = s;
    __syncthreads();
    if (tid == 0) {
        float t = 0.f;
        #pragma unroll
        for (int k = 0; k < 8; k++) t += rs[k];
        coeff_s = t / (1.0f + t) / sqrtf(t + 1e-9f);
    }
    __syncthreads();
    float co = coeff_s;
    #pragma unroll
    for (int j = 0; j < 8; j++) row[tid + 256 * j] = v[j] * co;
}

// ============================================================================
// b_update: b[cap,s] += x[cap,s,:] . v[cap,:]   (warp per s; v staged in smem)
// grid (S/8, C), block 256
// ============================================================================
__global__ void __launch_bounds__(256) b_update_kernel(const float* __restrict__ x) {
    const int cap = blockIdx.y;
    const int tid = threadIdx.x;
    __shared__ float vs[H_DIM];
    #pragma unroll
    for (int j = 0; j < 2; j++) {
        float4 vv = *(const float4*)(g_v + cap * H_DIM + (tid + 256 * j) * 4);
        *(float4*)(vs + (tid + 256 * j) * 4) = vv;
    }
    __syncthreads();

    const int warp = tid >> 5, lane = tid & 31;
    const int s = blockIdx.x * 8 + warp;
    const float4* xp = (const float4*)(x + ((size_t)cap * S_LEN + s) * H_DIM);
    const float4* vp = (const float4*)vs;
    float acc = 0.f;
    #pragma unroll 4
    for (int j = lane; j < H_DIM / 4; j += 32) {
        float4 ev = xp[j], cv = vp[j];
        acc = fmaf(ev.x, cv.x, acc);
        acc = fmaf(ev.y, cv.y, acc);
        acc = fmaf(ev.z, cv.z, acc);
        acc = fmaf(ev.w, cv.w, acc);
    }
    #pragma unroll
    for (int o = 16; o > 0; o >>= 1) acc += __shfl_xor_sync(0xffffffffu, acc, o);
    if (lane == 0) g_b[cap * S_LEN + s] += acc;
}

// ============================================================================
// kernel_launch
// ============================================================================
extern "C" void kernel_launch(void* const* d_in, const int* in_sizes, int n_in,
                              void* d_out, int out_size) {
    const float* x = (const float*)d_in[0];   // [64,128,2048] fp32
    const float* W = (const float*)d_in[1];   // [2048,2048] fp32
    float* out = (float*)d_out;               // [64,2048] fp32 — holds c

    float *u_ptr, *v_ptr, *wt_ptr;
    cudaGetSymbolAddress((void**)&u_ptr, g_u);
    cudaGetSymbolAddress((void**)&v_ptr, g_v);
    cudaGetSymbolAddress((void**)&wt_ptr, g_Wt);

    transpose_kernel<<<dim3(H_DIM / 32, H_DIM / 32), dim3(32, 8)>>>(W);
    zero_b_kernel<<<8, 1024>>>();

    for (int it = 0; it < 3; ++it) {
        u_kernel<<<dim3(H_DIM / 256, C_CAPS), 256>>>(x);
        dot_gemm_kernel<<<H_DIM / 16, 256>>>(u_ptr, wt_ptr, out);   // c = u @ W
        squash_kernel<<<C_CAPS, 256>>>(out);
        if (it < 2) {
            dot_gemm_kernel<<<H_DIM / 16, 256>>>(out, W, v_ptr);    // v = c @ W^T
            b_update_kernel<<<dim3(S_LEN / 8, C_CAPS), 256>>>(x);
        }
    }
}

// round 4
// speedup vs baseline: 1.3138x; 1.3138x over previous
#include <cuda_runtime.h>
#include <cstdint>

// ============================================================================
// Induction capsule routing, restructured (no e materialization) + split-K GEMM
//   c_i = (sum_s d_is x_is) @ W          (u = weighted x reduce; c = u@W)
//   b  += x · (W c)                      (v = c@W^T; b_cs = x_cs . v_c)
// ============================================================================

static constexpr int C_CAPS = 64;
static constexpr int S_LEN  = 128;
static constexpr int H_DIM  = 2048;
static constexpr int KSPLIT = 16;
static constexpr int KLEN   = H_DIM / KSPLIT;   // 128
static constexpr int SPAD   = 68;               // 272 B row stride: 16B-aligned, bank-rotating

// ---- scratch (device globals; allocation-free rule) ----
__device__ float g_b[C_CAPS * S_LEN];                       // logits
__device__ float g_u[C_CAPS * H_DIM];                       // weighted x sums
__device__ float g_v[C_CAPS * H_DIM];                       // W @ c
__device__ float g_Wt[(size_t)H_DIM * H_DIM];               // W^T (16 MB)
__device__ float g_part[KSPLIT][C_CAPS][H_DIM];             // split-K partials (8 MB)

// ============================================================================
// transpose: g_Wt[n][k] = W[k][n]
// ============================================================================
__global__ void transpose_kernel(const float* __restrict__ W) {
    __shared__ float t[32][33];
    int bx = blockIdx.x, by = blockIdx.y;
    int tx = threadIdx.x, ty = threadIdx.y;
    int col = bx * 32 + tx;
    #pragma unroll
    for (int j = 0; j < 32; j += 8)
        t[ty + j][tx] = W[(size_t)(by * 32 + ty + j) * H_DIM + col];
    __syncthreads();
    int ocol = by * 32 + tx;
    #pragma unroll
    for (int j = 0; j < 32; j += 8)
        g_Wt[(size_t)(bx * 32 + ty + j) * H_DIM + ocol] = t[tx][ty + j];
}

__global__ void zero_b_kernel() {
    int i = blockIdx.x * blockDim.x + threadIdx.x;
    if (i < C_CAPS * S_LEN) g_b[i] = 0.0f;
}

// ============================================================================
// u_kernel: d = softmax(b[cap,:]); u[cap,h] = sum_s d[s] * x[cap,s,h]
// ============================================================================
__global__ void __launch_bounds__(256) u_kernel(const float* __restrict__ x) {
    const int cap = blockIdx.y;
    const int tid = threadIdx.x;
    const int h = blockIdx.x * 256 + tid;
    __shared__ float d[S_LEN];

    if (tid < S_LEN) d[tid] = g_b[cap * S_LEN + tid];
    __syncthreads();
    if (tid < 32) {
        float x0 = d[tid], x1 = d[tid + 32], x2 = d[tid + 64], x3 = d[tid + 96];
        float mx = fmaxf(fmaxf(x0, x1), fmaxf(x2, x3));
        #pragma unroll
        for (int o = 16; o > 0; o >>= 1) mx = fmaxf(mx, __shfl_xor_sync(0xffffffffu, mx, o));
        float e0 = __expf(x0 - mx), e1 = __expf(x1 - mx);
        float e2 = __expf(x2 - mx), e3 = __expf(x3 - mx);
        float s = (e0 + e1) + (e2 + e3);
        #pragma unroll
        for (int o = 16; o > 0; o >>= 1) s += __shfl_xor_sync(0xffffffffu, s, o);
        float inv = 1.0f / s;
        d[tid] = e0 * inv; d[tid + 32] = e1 * inv; d[tid + 64] = e2 * inv; d[tid + 96] = e3 * inv;
    }
    __syncthreads();

    const float* xp = x + (size_t)cap * S_LEN * H_DIM + h;
    float a0 = 0.f, a1 = 0.f, a2 = 0.f, a3 = 0.f;
    #pragma unroll 8
    for (int s = 0; s < S_LEN; s += 4) {
        a0 = fmaf(d[s + 0], xp[(size_t)(s + 0) * H_DIM], a0);
        a1 = fmaf(d[s + 1], xp[(size_t)(s + 1) * H_DIM], a1);
        a2 = fmaf(d[s + 2], xp[(size_t)(s + 2) * H_DIM], a2);
        a3 = fmaf(d[s + 3], xp[(size_t)(s + 3) * H_DIM], a3);
    }
    g_u[cap * H_DIM + h] = (a0 + a1) + (a2 + a3);
}

// ============================================================================
// gemm_splitk: g_part[kz][m][j] = sum_{h in kz chunk} A[m][h] * B[j][h]
//   A [64,2048], B [2048,2048], both row-major K-contiguous.
//   grid (2048/64, KSPLIT) = (32, 16) = 512 CTAs, block 256.
//   Block tile 64m x 64j, thread tile 4x4, smem stored [k][m]/[k][j] with
//   16B-aligned padded rows so the inner loop is 2x lds.128 + 16 FFMA.
// ============================================================================
__global__ void __launch_bounds__(256) gemm_splitk_kernel(const float* __restrict__ A,
                                                          const float* __restrict__ B) {
    __shared__ float As[32][SPAD];
    __shared__ float Bs[32][SPAD];

    const int tid = threadIdx.x;
    const int j0 = blockIdx.x * 64;
    const int kz = blockIdx.y;
    const int k0 = kz * KLEN;

    const int m0  = (tid & 15) * 4;
    const int jl0 = (tid >> 4) * 4;

    // load slots: idx covers 64 rows x 8 k-groups (of 4 floats)
    const int lm  = (tid + 0)   >> 3, lk0 = ((tid + 0)   & 7) * 4;
    const int lm2 = (tid + 256) >> 3, lk2 = ((tid + 256) & 7) * 4;

    float acc[4][4] = {};

    for (int kc = 0; kc < KLEN; kc += 32) {
        float4 va0 = *(const float4*)(A + (size_t)lm  * H_DIM + k0 + kc + lk0);
        float4 vb0 = *(const float4*)(B + (size_t)(j0 + lm)  * H_DIM + k0 + kc + lk0);
        float4 va1 = *(const float4*)(A + (size_t)lm2 * H_DIM + k0 + kc + lk2);
        float4 vb1 = *(const float4*)(B + (size_t)(j0 + lm2) * H_DIM + k0 + kc + lk2);

        As[lk0 + 0][lm] = va0.x; As[lk0 + 1][lm] = va0.y;
        As[lk0 + 2][lm] = va0.z; As[lk0 + 3][lm] = va0.w;
        Bs[lk0 + 0][lm] = vb0.x; Bs[lk0 + 1][lm] = vb0.y;
        Bs[lk0 + 2][lm] = vb0.z; Bs[lk0 + 3][lm] = vb0.w;
        As[lk2 + 0][lm2] = va1.x; As[lk2 + 1][lm2] = va1.y;
        As[lk2 + 2][lm2] = va1.z; As[lk2 + 3][lm2] = va1.w;
        Bs[lk2 + 0][lm2] = vb1.x; Bs[lk2 + 1][lm2] = vb1.y;
        Bs[lk2 + 2][lm2] = vb1.z; Bs[lk2 + 3][lm2] = vb1.w;
        __syncthreads();

        #pragma unroll
        for (int hh = 0; hh < 32; hh++) {
            float4 av = *(const float4*)&As[hh][m0];
            float4 bv = *(const float4*)&Bs[hh][jl0];
            acc[0][0] = fmaf(av.x, bv.x, acc[0][0]);
            acc[0][1] = fmaf(av.x, bv.y, acc[0][1]);
            acc[0][2] = fmaf(av.x, bv.z, acc[0][2]);
            acc[0][3] = fmaf(av.x, bv.w, acc[0][3]);
            acc[1][0] = fmaf(av.y, bv.x, acc[1][0]);
            acc[1][1] = fmaf(av.y, bv.y, acc[1][1]);
            acc[1][2] = fmaf(av.y, bv.z, acc[1][2]);
            acc[1][3] = fmaf(av.y, bv.w, acc[1][3]);
            acc[2][0] = fmaf(av.z, bv.x, acc[2][0]);
            acc[2][1] = fmaf(av.z, bv.y, acc[2][1]);
            acc[2][2] = fmaf(av.z, bv.z, acc[2][2]);
            acc[2][3] = fmaf(av.z, bv.w, acc[2][3]);
            acc[3][0] = fmaf(av.w, bv.x, acc[3][0]);
            acc[3][1] = fmaf(av.w, bv.y, acc[3][1]);
            acc[3][2] = fmaf(av.w, bv.z, acc[3][2]);
            acc[3][3] = fmaf(av.w, bv.w, acc[3][3]);
        }
        __syncthreads();
    }

    #pragma unroll
    for (int i = 0; i < 4; i++)
        *(float4*)&g_part[kz][m0 + i][j0 + jl0] =
            make_float4(acc[i][0], acc[i][1], acc[i][2], acc[i][3]);
}

// ============================================================================
// reduce_c_squash: c[cap][:] = squash( sum_z g_part[z][cap][:] )
//   grid 64 (one block per capsule row), block 256.
// ============================================================================
__global__ void __launch_bounds__(256) reduce_c_squash_kernel(float* __restrict__ out) {
    const int cap = blockIdx.x;
    const int tid = threadIdx.x;

    float4 sv[2];
    float nrm = 0.f;
    #pragma unroll
    for (int r = 0; r < 2; r++) {
        int j = (tid + 256 * r) * 4;
        float4 a = make_float4(0.f, 0.f, 0.f, 0.f);
        #pragma unroll
        for (int z = 0; z < KSPLIT; z++) {
            float4 p = *(const float4*)&g_part[z][cap][j];
            a.x += p.x; a.y += p.y; a.z += p.z; a.w += p.w;
        }
        sv[r] = a;
        nrm = fmaf(a.x, a.x, nrm); nrm = fmaf(a.y, a.y, nrm);
        nrm = fmaf(a.z, a.z, nrm); nrm = fmaf(a.w, a.w, nrm);
    }
    #pragma unroll
    for (int o = 16; o > 0; o >>= 1) nrm += __shfl_xor_sync(0xffffffffu, nrm, o);
    __shared__ float rs[8];
    __shared__ float coeff_s;
    if ((tid & 31) == 0) rs[tid >> 5] = nrm;
    __syncthreads();
    if (tid == 0) {
        float t = 0.f;
        #pragma unroll
        for (int k = 0; k < 8; k++) t += rs[k];
        coeff_s = t / (1.0f + t) / sqrtf(t + 1e-9f);
    }
    __syncthreads();
    float co = coeff_s;
    #pragma unroll
    for (int r = 0; r < 2; r++) {
        int j = (tid + 256 * r) * 4;
        *(float4*)(out + cap * H_DIM + j) =
            make_float4(sv[r].x * co, sv[r].y * co, sv[r].z * co, sv[r].w * co);
    }
}

// ============================================================================
// reduce_v: v[m][j] = sum_z g_part[z][m][j]   (grid 128, block 256, f4/thread)
// ============================================================================
__global__ void __launch_bounds__(256) reduce_v_kernel() {
    int idx4 = blockIdx.x * 256 + threadIdx.x;       // 0 .. 64*512-1
    int m = idx4 >> 9;
    int j = (idx4 & 511) * 4;
    float4 a = make_float4(0.f, 0.f, 0.f, 0.f);
    #pragma unroll
    for (int z = 0; z < KSPLIT; z++) {
        float4 p = *(const float4*)&g_part[z][m][j];
        a.x += p.x; a.y += p.y; a.z += p.z; a.w += p.w;
    }
    *(float4*)&g_v[m * H_DIM + j] = a;
}

// ============================================================================
// b_update: b[cap,s] += x[cap,s,:] . v[cap,:]   (warp per s; v staged in smem)
// ============================================================================
__global__ void __launch_bounds__(256) b_update_kernel(const float* __restrict__ x) {
    const int cap = blockIdx.y;
    const int tid = threadIdx.x;
    __shared__ float vs[H_DIM];
    #pragma unroll
    for (int j = 0; j < 2; j++) {
        float4 vv = *(const float4*)(g_v + cap * H_DIM + (tid + 256 * j) * 4);
        *(float4*)(vs + (tid + 256 * j) * 4) = vv;
    }
    __syncthreads();

    const int warp = tid >> 5, lane = tid & 31;
    const int s = blockIdx.x * 8 + warp;
    const float4* xp = (const float4*)(x + ((size_t)cap * S_LEN + s) * H_DIM);
    const float4* vp = (const float4*)vs;
    float acc = 0.f;
    #pragma unroll 4
    for (int j = lane; j < H_DIM / 4; j += 32) {
        float4 ev = xp[j], cv = vp[j];
        acc = fmaf(ev.x, cv.x, acc);
        acc = fmaf(ev.y, cv.y, acc);
        acc = fmaf(ev.z, cv.z, acc);
        acc = fmaf(ev.w, cv.w, acc);
    }
    #pragma unroll
    for (int o = 16; o > 0; o >>= 1) acc += __shfl_xor_sync(0xffffffffu, acc, o);
    if (lane == 0) g_b[cap * S_LEN + s] += acc;
}

// ============================================================================
// kernel_launch
// ============================================================================
extern "C" void kernel_launch(void* const* d_in, const int* in_sizes, int n_in,
                              void* d_out, int out_size) {
    const float* x = (const float*)d_in[0];   // [64,128,2048] fp32
    const float* W = (const float*)d_in[1];   // [2048,2048] fp32
    float* out = (float*)d_out;               // [64,2048] fp32 — holds c

    float *u_ptr, *wt_ptr;
    cudaGetSymbolAddress((void**)&u_ptr, g_u);
    cudaGetSymbolAddress((void**)&wt_ptr, g_Wt);

    const dim3 gemm_grid(H_DIM / 64, KSPLIT);

    transpose_kernel<<<dim3(H_DIM / 32, H_DIM / 32), dim3(32, 8)>>>(W);
    zero_b_kernel<<<8, 1024>>>();

    for (int it = 0; it < 3; ++it) {
        u_kernel<<<dim3(H_DIM / 256, C_CAPS), 256>>>(x);
        gemm_splitk_kernel<<<gemm_grid, 256>>>(u_ptr, wt_ptr);      // c = u @ W
        reduce_c_squash_kernel<<<C_CAPS, 256>>>(out);
        if (it < 2) {
            gemm_splitk_kernel<<<gemm_grid, 256>>>(out, W);         // v = c @ W^T
            reduce_v_kernel<<<C_CAPS * H_DIM / 1024, 256>>>();
            b_update_kernel<<<dim3(S_LEN / 8, C_CAPS), 256>>>(x);
        }
    }
}

// round 5
// speedup vs baseline: 1.6359x; 1.2451x over previous
#include <cuda_runtime.h>
#include <cstdint>

// ============================================================================
// Induction capsule routing, restructured (no e materialization):
//   c_i = (sum_s d_is x_is) @ W      (u_kernel; gemm NT: B=W, k-rows j-contig)
//   b  += x . (W c)                  (gemm TN: B=W, j-rows k-contig; b_update)
// Split-K FFMA GEMM, double-buffered smem, thread tile 4m x 8j. No transpose.
// ============================================================================

static constexpr int C_CAPS = 64;
static constexpr int S_LEN  = 128;
static constexpr int H_DIM  = 2048;
static constexpr int KSPLIT = 16;
static constexpr int KLEN   = H_DIM / KSPLIT;   // 128 (8 chunks of 16)
static constexpr int NCHUNK = KLEN / 16;        // 8
static constexpr int SPAD   = 68;               // 272B rows: 16B-aligned, bank-rotating

// ---- scratch (device globals; allocation-free rule) ----
__device__ float g_b[C_CAPS * S_LEN];                       // logits
__device__ float g_u[C_CAPS * H_DIM];                       // weighted x sums
__device__ float g_v[C_CAPS * H_DIM];                       // W @ c
__device__ float g_part[KSPLIT][C_CAPS][H_DIM];             // split-K partials (8 MB)

__global__ void zero_b_kernel() {
    int i = blockIdx.x * blockDim.x + threadIdx.x;
    if (i < C_CAPS * S_LEN) g_b[i] = 0.0f;
}

// ============================================================================
// u_kernel: d = softmax(b[cap,:]); u[cap,h] = sum_s d[s] * x[cap,s,h]
// ============================================================================
__global__ void __launch_bounds__(256) u_kernel(const float* __restrict__ x) {
    const int cap = blockIdx.y;
    const int tid = threadIdx.x;
    const int h = blockIdx.x * 256 + tid;
    __shared__ float d[S_LEN];

    if (tid < S_LEN) d[tid] = g_b[cap * S_LEN + tid];
    __syncthreads();
    if (tid < 32) {
        float x0 = d[tid], x1 = d[tid + 32], x2 = d[tid + 64], x3 = d[tid + 96];
        float mx = fmaxf(fmaxf(x0, x1), fmaxf(x2, x3));
        #pragma unroll
        for (int o = 16; o > 0; o >>= 1) mx = fmaxf(mx, __shfl_xor_sync(0xffffffffu, mx, o));
        float e0 = __expf(x0 - mx), e1 = __expf(x1 - mx);
        float e2 = __expf(x2 - mx), e3 = __expf(x3 - mx);
        float s = (e0 + e1) + (e2 + e3);
        #pragma unroll
        for (int o = 16; o > 0; o >>= 1) s += __shfl_xor_sync(0xffffffffu, s, o);
        float inv = 1.0f / s;
        d[tid] = e0 * inv; d[tid + 32] = e1 * inv; d[tid + 64] = e2 * inv; d[tid + 96] = e3 * inv;
    }
    __syncthreads();

    const float* xp = x + (size_t)cap * S_LEN * H_DIM + h;
    float a0 = 0.f, a1 = 0.f, a2 = 0.f, a3 = 0.f;
    #pragma unroll 8
    for (int s = 0; s < S_LEN; s += 4) {
        a0 = fmaf(d[s + 0], xp[(size_t)(s + 0) * H_DIM], a0);
        a1 = fmaf(d[s + 1], xp[(size_t)(s + 1) * H_DIM], a1);
        a2 = fmaf(d[s + 2], xp[(size_t)(s + 2) * H_DIM], a2);
        a3 = fmaf(d[s + 3], xp[(size_t)(s + 3) * H_DIM], a3);
    }
    g_u[cap * H_DIM + h] = (a0 + a1) + (a2 + a3);
}

// ============================================================================
// gemm_splitk<BK_CONTIG>:
//   g_part[kz][m][j] = sum_{k in chunk kz} A[m][k] * Bval(k, j)
//   BK_CONTIG=true  (TN): Bval(k,j) = B[(j0+j)*H + k]      (v = c @ W^T)
//   BK_CONTIG=false (NT): Bval(k,j) = B[k*H + (j0+j)]      (c = u @ W)
//   grid (32, 16) = 512 CTAs, block 128. Tile 64m x 64j, thread 4m x 8j.
//   k-chunk 16, double-buffered smem, ONE __syncthreads per chunk.
// ============================================================================
template <bool BK_CONTIG>
__global__ void __launch_bounds__(128) gemm_splitk_kernel(const float* __restrict__ A,
                                                          const float* __restrict__ B) {
    __shared__ float As[2][16][SPAD];
    __shared__ float Bs[2][16][SPAD];

    const int tid = threadIdx.x;
    const int j0 = blockIdx.x * 64;
    const int kz = blockIdx.y;
    const int k0 = kz * KLEN;

    const int m0  = (tid & 15) * 4;        // 16 m-groups x 4
    const int jl0 = (tid >> 4) * 8;        // 8 j-groups x 8

    // ---- per-thread load slots (2 each for A and B) ----
    // A: 64 m-rows x 4 k-groups(float4) = 256 slots
    int am[2], akg[2];
    const float* aptr[2];
    #pragma unroll
    for (int i = 0; i < 2; i++) {
        int s = tid + 128 * i;
        am[i] = s >> 2; akg[i] = s & 3;
        aptr[i] = A + (size_t)am[i] * H_DIM + k0 + akg[i] * 4;
    }
    // B slots
    int br[2], bg[2];
    const float* bptr[2];
    #pragma unroll
    for (int i = 0; i < 2; i++) {
        int s = tid + 128 * i;
        if (BK_CONTIG) {           // B[j][k]: 64 j-rows x 4 k-groups
            br[i] = s >> 2; bg[i] = s & 3;
            bptr[i] = B + (size_t)(j0 + br[i]) * H_DIM + k0 + bg[i] * 4;
        } else {                   // B[k][j]: 16 k-rows x 16 j-groups
            br[i] = s >> 4; bg[i] = s & 15;
            bptr[i] = B + (size_t)(k0 + br[i]) * H_DIM + j0 + bg[i] * 4;
        }
    }

    float4 ar[2], brv[2];
    // prologue: chunk 0 loads
    #pragma unroll
    for (int i = 0; i < 2; i++) {
        ar[i]  = *(const float4*)(aptr[i]);
        brv[i] = *(const float4*)(bptr[i]);
    }

    float acc[4][8] = {};

    for (int kc = 0; kc < NCHUNK; kc++) {
        const int cur = kc & 1;
        // store current regs -> smem[cur]
        #pragma unroll
        for (int i = 0; i < 2; i++) {
            float* asl = &As[cur][akg[i] * 4][am[i]];
            asl[0 * SPAD] = ar[i].x; asl[1 * SPAD] = ar[i].y;
            asl[2 * SPAD] = ar[i].z; asl[3 * SPAD] = ar[i].w;
            if (BK_CONTIG) {
                float* bsl = &Bs[cur][bg[i] * 4][br[i]];
                bsl[0 * SPAD] = brv[i].x; bsl[1 * SPAD] = brv[i].y;
                bsl[2 * SPAD] = brv[i].z; bsl[3 * SPAD] = brv[i].w;
            } else {
                *(float4*)&Bs[cur][br[i]][bg[i] * 4] = brv[i];
            }
        }
        __syncthreads();

        // issue next-chunk loads (overlap with compute below)
        if (kc + 1 < NCHUNK) {
            const int koff = (kc + 1) * 16;
            #pragma unroll
            for (int i = 0; i < 2; i++) {
                ar[i] = *(const float4*)(aptr[i] + koff);
                brv[i] = BK_CONTIG
                    ? *(const float4*)(bptr[i] + koff)
                    : *(const float4*)(bptr[i] + (size_t)koff * H_DIM);
            }
        }

        #pragma unroll
        for (int k = 0; k < 16; k++) {
            const float4 av  = *(const float4*)&As[cur][k][m0];
            const float4 bv0 = *(const float4*)&Bs[cur][k][jl0];
            const float4 bv1 = *(const float4*)&Bs[cur][k][jl0 + 4];
            const float a4[4] = {av.x, av.y, av.z, av.w};
            const float b8[8] = {bv0.x, bv0.y, bv0.z, bv0.w, bv1.x, bv1.y, bv1.z, bv1.w};
            #pragma unroll
            for (int i = 0; i < 4; i++)
                #pragma unroll
                for (int j = 0; j < 8; j++)
                    acc[i][j] = fmaf(a4[i], b8[j], acc[i][j]);
        }
        // next iteration stores to the other buffer; its last readers were
        // iteration kc-1, already ordered before this iteration's barrier.
        if (kc + 1 < NCHUNK) __syncthreads();
    }

    #pragma unroll
    for (int i = 0; i < 4; i++) {
        *(float4*)&g_part[kz][m0 + i][j0 + jl0] =
            make_float4(acc[i][0], acc[i][1], acc[i][2], acc[i][3]);
        *(float4*)&g_part[kz][m0 + i][j0 + jl0 + 4] =
            make_float4(acc[i][4], acc[i][5], acc[i][6], acc[i][7]);
    }
}

// ============================================================================
// reduce_c_squash: c[cap][:] = squash( sum_z g_part[z][cap][:] )
// ============================================================================
__global__ void __launch_bounds__(256) reduce_c_squash_kernel(float* __restrict__ out) {
    const int cap = blockIdx.x;
    const int tid = threadIdx.x;

    float4 sv[2];
    float nrm = 0.f;
    #pragma unroll
    for (int r = 0; r < 2; r++) {
        int j = (tid + 256 * r) * 4;
        float4 a = make_float4(0.f, 0.f, 0.f, 0.f);
        #pragma unroll
        for (int z = 0; z < KSPLIT; z++) {
            float4 p = *(const float4*)&g_part[z][cap][j];
            a.x += p.x; a.y += p.y; a.z += p.z; a.w += p.w;
        }
        sv[r] = a;
        nrm = fmaf(a.x, a.x, nrm); nrm = fmaf(a.y, a.y, nrm);
        nrm = fmaf(a.z, a.z, nrm); nrm = fmaf(a.w, a.w, nrm);
    }
    #pragma unroll
    for (int o = 16; o > 0; o >>= 1) nrm += __shfl_xor_sync(0xffffffffu, nrm, o);
    __shared__ float rs[8];
    __shared__ float coeff_s;
    if ((tid & 31) == 0) rs[tid >> 5] = nrm;
    __syncthreads();
    if (tid == 0) {
        float t = 0.f;
        #pragma unroll
        for (int k = 0; k < 8; k++) t += rs[k];
        coeff_s = t / (1.0f + t) / sqrtf(t + 1e-9f);
    }
    __syncthreads();
    float co = coeff_s;
    #pragma unroll
    for (int r = 0; r < 2; r++) {
        int j = (tid + 256 * r) * 4;
        *(float4*)(out + cap * H_DIM + j) =
            make_float4(sv[r].x * co, sv[r].y * co, sv[r].z * co, sv[r].w * co);
    }
}

// ============================================================================
// reduce_v: v[m][j] = sum_z g_part[z][m][j]
// ============================================================================
__global__ void __launch_bounds__(256) reduce_v_kernel() {
    int idx4 = blockIdx.x * 256 + threadIdx.x;       // 0 .. 64*512-1
    int m = idx4 >> 9;
    int j = (idx4 & 511) * 4;
    float4 a = make_float4(0.f, 0.f, 0.f, 0.f);
    #pragma unroll
    for (int z = 0; z < KSPLIT; z++) {
        float4 p = *(const float4*)&g_part[z][m][j];
        a.x += p.x; a.y += p.y; a.z += p.z; a.w += p.w;
    }
    *(float4*)&g_v[m * H_DIM + j] = a;
}

// ============================================================================
// b_update: b[cap,s] += x[cap,s,:] . v[cap,:]   (warp per s; v staged in smem)
// ============================================================================
__global__ void __launch_bounds__(256) b_update_kernel(const float* __restrict__ x) {
    const int cap = blockIdx.y;
    const int tid = threadIdx.x;
    __shared__ float vs[H_DIM];
    #pragma unroll
    for (int j = 0; j < 2; j++) {
        float4 vv = *(const float4*)(g_v + cap * H_DIM + (tid + 256 * j) * 4);
        *(float4*)(vs + (tid + 256 * j) * 4) = vv;
    }
    __syncthreads();

    const int warp = tid >> 5, lane = tid & 31;
    const int s = blockIdx.x * 8 + warp;
    const float4* xp = (const float4*)(x + ((size_t)cap * S_LEN + s) * H_DIM);
    const float4* vp = (const float4*)vs;
    float acc = 0.f;
    #pragma unroll 4
    for (int j = lane; j < H_DIM / 4; j += 32) {
        float4 ev = xp[j], cv = vp[j];
        acc = fmaf(ev.x, cv.x, acc);
        acc = fmaf(ev.y, cv.y, acc);
        acc = fmaf(ev.z, cv.z, acc);
        acc = fmaf(ev.w, cv.w, acc);
    }
    #pragma unroll
    for (int o = 16; o > 0; o >>= 1) acc += __shfl_xor_sync(0xffffffffu, acc, o);
    if (lane == 0) g_b[cap * S_LEN + s] += acc;
}

// ============================================================================
// kernel_launch
// ============================================================================
extern "C" void kernel_launch(void* const* d_in, const int* in_sizes, int n_in,
                              void* d_out, int out_size) {
    const float* x = (const float*)d_in[0];   // [64,128,2048] fp32
    const float* W = (const float*)d_in[1];   // [2048,2048] fp32
    float* out = (float*)d_out;               // [64,2048] fp32 — holds c

    float* u_ptr;
    cudaGetSymbolAddress((void**)&u_ptr, g_u);

    const dim3 gemm_grid(H_DIM / 64, KSPLIT);

    zero_b_kernel<<<8, 1024>>>();

    for (int it = 0; it < 3; ++it) {
        u_kernel<<<dim3(H_DIM / 256, C_CAPS), 256>>>(x);
        gemm_splitk_kernel<false><<<gemm_grid, 128>>>(u_ptr, W);    // c = u @ W
        reduce_c_squash_kernel<<<C_CAPS, 256>>>(out);
        if (it < 2) {
            gemm_splitk_kernel<true><<<gemm_grid, 128>>>(out, W);   // v = c @ W^T
            reduce_v_kernel<<<C_CAPS * H_DIM / 1024, 256>>>();
            b_update_kernel<<<dim3(S_LEN / 8, C_CAPS), 256>>>(x);
        }
    }
}

// round 6
// speedup vs baseline: 1.6846x; 1.0298x over previous
#include <cuda_runtime.h>
#include <cstdint>

// ============================================================================
// Induction capsule routing, restructured (no e materialization):
//   c_i = (sum_s d_is x_is) @ W      (u_kernel; gemm NT: B=W, k-rows j-contig)
//   b  += x . (W c)                  (gemm TN: B=W, j-rows k-contig; b_update)
// Split-K GEMM on mma.sync m16n8k8 tf32 with 3xTF32 split (~fp32 accuracy).
// ============================================================================

static constexpr int C_CAPS = 64;
static constexpr int S_LEN  = 128;
static constexpr int H_DIM  = 2048;
static constexpr int KSPLIT = 16;
static constexpr int KLEN   = H_DIM / KSPLIT;   // 128 (8 chunks of 16)
static constexpr int NCHUNK = KLEN / 16;        // 8
static constexpr int SP     = 20;               // smem row pitch (floats): 80B, 16B-aligned

// ---- scratch (device globals; allocation-free rule) ----
__device__ float g_b[C_CAPS * S_LEN];                       // logits
__device__ float g_u[C_CAPS * H_DIM];                       // weighted x sums
__device__ float g_v[C_CAPS * H_DIM];                       // W @ c
__device__ float g_part[KSPLIT][C_CAPS][H_DIM];             // split-K partials (8 MB)
__device__ float g_nrm2[C_CAPS][16];                        // per-block norm partials

__global__ void zero_b_kernel() {
    int i = blockIdx.x * blockDim.x + threadIdx.x;
    if (i < C_CAPS * S_LEN) g_b[i] = 0.0f;
}

// ============================================================================
// u_kernel: d = softmax(b[cap,:]); u[cap,h] = sum_s d[s] * x[cap,s,h]
// ============================================================================
__global__ void __launch_bounds__(256) u_kernel(const float* __restrict__ x) {
    const int cap = blockIdx.y;
    const int tid = threadIdx.x;
    const int h = blockIdx.x * 256 + tid;
    __shared__ float d[S_LEN];

    if (tid < S_LEN) d[tid] = g_b[cap * S_LEN + tid];
    __syncthreads();
    if (tid < 32) {
        float x0 = d[tid], x1 = d[tid + 32], x2 = d[tid + 64], x3 = d[tid + 96];
        float mx = fmaxf(fmaxf(x0, x1), fmaxf(x2, x3));
        #pragma unroll
        for (int o = 16; o > 0; o >>= 1) mx = fmaxf(mx, __shfl_xor_sync(0xffffffffu, mx, o));
        float e0 = __expf(x0 - mx), e1 = __expf(x1 - mx);
        float e2 = __expf(x2 - mx), e3 = __expf(x3 - mx);
        float s = (e0 + e1) + (e2 + e3);
        #pragma unroll
        for (int o = 16; o > 0; o >>= 1) s += __shfl_xor_sync(0xffffffffu, s, o);
        float inv = 1.0f / s;
        d[tid] = e0 * inv; d[tid + 32] = e1 * inv; d[tid + 64] = e2 * inv; d[tid + 96] = e3 * inv;
    }
    __syncthreads();

    const float* xp = x + (size_t)cap * S_LEN * H_DIM + h;
    float a0 = 0.f, a1 = 0.f, a2 = 0.f, a3 = 0.f;
    #pragma unroll 8
    for (int s = 0; s < S_LEN; s += 4) {
        a0 = fmaf(d[s + 0], xp[(size_t)(s + 0) * H_DIM], a0);
        a1 = fmaf(d[s + 1], xp[(size_t)(s + 1) * H_DIM], a1);
        a2 = fmaf(d[s + 2], xp[(size_t)(s + 2) * H_DIM], a2);
        a3 = fmaf(d[s + 3], xp[(size_t)(s + 3) * H_DIM], a3);
    }
    g_u[cap * H_DIM + h] = (a0 + a1) + (a2 + a3);
}

// ============================================================================
// 3xTF32 helpers
// ============================================================================
static __device__ __forceinline__ void tf32_split(float f, uint32_t& hi, uint32_t& lo) {
    asm("cvt.rna.tf32.f32 %0, %1;" : "=r"(hi) : "f"(f));
    float r = f - __uint_as_float(hi);
    asm("cvt.rna.tf32.f32 %0, %1;" : "=r"(lo) : "f"(r));
}
static __device__ __forceinline__ void mma_tf32(float* c, const uint32_t* a,
                                                uint32_t b0, uint32_t b1) {
    asm("mma.sync.aligned.m16n8k8.row.col.f32.tf32.tf32.f32 "
        "{%0,%1,%2,%3}, {%4,%5,%6,%7}, {%8,%9}, {%0,%1,%2,%3};"
        : "+f"(c[0]), "+f"(c[1]), "+f"(c[2]), "+f"(c[3])
        : "r"(a[0]), "r"(a[1]), "r"(a[2]), "r"(a[3]), "r"(b0), "r"(b1));
}

// ============================================================================
// gemm_mma<BK_CONTIG>: g_part[kz][m][j] = sum_{k in chunk kz} A[m][k]*Bval(k,j)
//   BK_CONTIG=true  (TN): Bval(k,j) = B[(j0+j)*H + k]      (v = c @ W^T)
//   BK_CONTIG=false (NT): Bval(k,j) = B[k*H + (j0+j)]      (c = u @ W)
//   grid (32, 16) = 512 CTAs, block 128 (4 warps).
//   CTA tile: M=64 (full), N=64, K=128 in 8 chunks of 16; double-buffered smem.
//   Warp w -> m rows [16w,16w+16); 8 n-tiles of 8; 3 mma per (k8, n-tile).
// ============================================================================
template <bool BK_CONTIG>
__global__ void __launch_bounds__(128) gemm_mma_kernel(const float* __restrict__ A,
                                                       const float* __restrict__ B) {
    __shared__ float As[2][64][SP];
    __shared__ float Bs[2][64][SP];

    const int tid = threadIdx.x;
    const int lane = tid & 31;
    const int w = tid >> 5;
    const int j0 = blockIdx.x * 64;
    const int kz = blockIdx.y;
    const int k0 = kz * KLEN;

    // ---- staging slots (2 per thread for each of A, B) ----
    const int am0 = tid >> 2,           ak0 = (tid & 3) * 4;
    const int am1 = (tid + 128) >> 2,   ak1 = ((tid + 128) & 3) * 4;
    const float* ap0 = A + (size_t)am0 * H_DIM + k0 + ak0;
    const float* ap1 = A + (size_t)am1 * H_DIM + k0 + ak1;

    int br0, bg0, br1, bg1;
    const float *bp0, *bp1;
    if (BK_CONTIG) {            // B[j][k]: 64 j-rows x 4 k-groups
        br0 = tid >> 2;          bg0 = (tid & 3) * 4;
        br1 = (tid + 128) >> 2;  bg1 = ((tid + 128) & 3) * 4;
        bp0 = B + (size_t)(j0 + br0) * H_DIM + k0 + bg0;
        bp1 = B + (size_t)(j0 + br1) * H_DIM + k0 + bg1;
    } else {                    // B[k][j]: 16 k-rows x 16 j-groups
        br0 = tid >> 4;          bg0 = (tid & 15) * 4;
        br1 = (tid + 128) >> 4;  bg1 = ((tid + 128) & 15) * 4;
        bp0 = B + (size_t)(k0 + br0) * H_DIM + j0 + bg0;
        bp1 = B + (size_t)(k0 + br1) * H_DIM + j0 + bg1;
    }

    // prologue: chunk 0
    float4 ar0 = *(const float4*)ap0, ar1 = *(const float4*)ap1;
    float4 br0v = *(const float4*)bp0, br1v = *(const float4*)bp1;

    const int g = lane >> 2, t = lane & 3;
    const int mrow = w * 16 + g;

    float acc[8][4] = {};

    for (int kc = 0; kc < NCHUNK; kc++) {
        const int cur = kc & 1;
        *(float4*)&As[cur][am0][ak0] = ar0;
        *(float4*)&As[cur][am1][ak1] = ar1;
        if (BK_CONTIG) {
            *(float4*)&Bs[cur][br0][bg0] = br0v;
            *(float4*)&Bs[cur][br1][bg1] = br1v;
        } else {
            Bs[cur][bg0 + 0][br0] = br0v.x; Bs[cur][bg0 + 1][br0] = br0v.y;
            Bs[cur][bg0 + 2][br0] = br0v.z; Bs[cur][bg0 + 3][br0] = br0v.w;
            Bs[cur][bg1 + 0][br1] = br1v.x; Bs[cur][bg1 + 1][br1] = br1v.y;
            Bs[cur][bg1 + 2][br1] = br1v.z; Bs[cur][bg1 + 3][br1] = br1v.w;
        }
        __syncthreads();

        if (kc + 1 < NCHUNK) {
            const int ko = (kc + 1) * 16;
            ar0 = *(const float4*)(ap0 + ko);
            ar1 = *(const float4*)(ap1 + ko);
            if (BK_CONTIG) {
                br0v = *(const float4*)(bp0 + ko);
                br1v = *(const float4*)(bp1 + ko);
            } else {
                br0v = *(const float4*)(bp0 + (size_t)ko * H_DIM);
                br1v = *(const float4*)(bp1 + (size_t)ko * H_DIM);
            }
        }

        #pragma unroll
        for (int kk = 0; kk < 16; kk += 8) {
            // A fragment (m16k8, row-major): conflict-free (pitch 20 verified)
            float fa0 = As[cur][mrow    ][kk + t];
            float fa1 = As[cur][mrow + 8][kk + t];
            float fa2 = As[cur][mrow    ][kk + t + 4];
            float fa3 = As[cur][mrow + 8][kk + t + 4];
            uint32_t ah[4], al[4];
            tf32_split(fa0, ah[0], al[0]);
            tf32_split(fa1, ah[1], al[1]);
            tf32_split(fa2, ah[2], al[2]);
            tf32_split(fa3, ah[3], al[3]);
            #pragma unroll
            for (int nt = 0; nt < 8; nt++) {
                float fb0 = Bs[cur][nt * 8 + g][kk + t];
                float fb1 = Bs[cur][nt * 8 + g][kk + t + 4];
                uint32_t bh0, bl0, bh1, bl1;
                tf32_split(fb0, bh0, bl0);
                tf32_split(fb1, bh1, bl1);
                mma_tf32(acc[nt], al, bh0, bh1);   // lo*hi
                mma_tf32(acc[nt], ah, bl0, bl1);   // hi*lo
                mma_tf32(acc[nt], ah, bh0, bh1);   // hi*hi
            }
        }
        // single barrier per chunk: next store targets the other buffer whose
        // readers all finished before THIS chunk's barrier.
    }

    // epilogue: c0=(g,2t) c1=(g,2t+1) c2=(g+8,2t) c3=(g+8,2t+1) per n-tile
    #pragma unroll
    for (int nt = 0; nt < 8; nt++) {
        const int col = j0 + nt * 8 + 2 * t;
        *(float2*)&g_part[kz][mrow    ][col] = make_float2(acc[nt][0], acc[nt][1]);
        *(float2*)&g_part[kz][mrow + 8][col] = make_float2(acc[nt][2], acc[nt][3]);
    }
}

// ============================================================================
// reduce_c_norm: out[cap][j] = sum_z g_part[z][cap][j]; g_nrm2[cap][jb] = ||.||^2 part
//   grid (16, 64) = 1024 CTAs, block 128 (one j per thread)
// ============================================================================
__global__ void __launch_bounds__(128) reduce_c_norm_kernel(float* __restrict__ out) {
    const int cap = blockIdx.y;
    const int jb = blockIdx.x;
    const int tid = threadIdx.x;
    const int j = jb * 128 + tid;

    float v = 0.f;
    #pragma unroll
    for (int z = 0; z < KSPLIT; z++) v += g_part[z][cap][j];
    out[cap * H_DIM + j] = v;

    float sq = v * v;
    #pragma unroll
    for (int o = 16; o > 0; o >>= 1) sq += __shfl_xor_sync(0xffffffffu, sq, o);
    __shared__ float ws[4];
    if ((tid & 31) == 0) ws[tid >> 5] = sq;
    __syncthreads();
    if (tid == 0) g_nrm2[cap][jb] = (ws[0] + ws[1]) + (ws[2] + ws[3]);
}

// ============================================================================
// squash_scale: coeff from 16 norm partials; scale out row in place. grid 64.
// ============================================================================
__global__ void __launch_bounds__(256) squash_scale_kernel(float* __restrict__ out) {
    const int cap = blockIdx.x;
    const int tid = threadIdx.x;
    __shared__ float coeff_s;
    if (tid == 0) {
        float s = 0.f;
        #pragma unroll
        for (int k = 0; k < 16; k++) s += g_nrm2[cap][k];
        coeff_s = s / (1.0f + s) / sqrtf(s + 1e-9f);
    }
    __syncthreads();
    const float co = coeff_s;
    float* row = out + cap * H_DIM;
    #pragma unroll
    for (int r = 0; r < 2; r++) {
        int j = (tid + 256 * r) * 4;
        float4 v = *(float4*)(row + j);
        *(float4*)(row + j) = make_float4(v.x * co, v.y * co, v.z * co, v.w * co);
    }
}

// ============================================================================
// reduce_v: v[m][j] = sum_z g_part[z][m][j]   (grid 512, block 256, scalar)
// ============================================================================
__global__ void __launch_bounds__(256) reduce_v_kernel() {
    const int idx = blockIdx.x * 256 + threadIdx.x;   // 0 .. 131071
    const int m = idx >> 11;
    const int j = idx & 2047;
    float v = 0.f;
    #pragma unroll
    for (int z = 0; z < KSPLIT; z++) v += g_part[z][m][j];
    g_v[m * H_DIM + j] = v;
}

// ============================================================================
// b_update: b[cap,s] += x[cap,s,:] . v[cap,:]   (warp per s; v staged in smem)
// ============================================================================
__global__ void __launch_bounds__(256) b_update_kernel(const float* __restrict__ x) {
    const int cap = blockIdx.y;
    const int tid = threadIdx.x;
    __shared__ float vs[H_DIM];
    #pragma unroll
    for (int j = 0; j < 2; j++) {
        float4 vv = *(const float4*)(g_v + cap * H_DIM + (tid + 256 * j) * 4);
        *(float4*)(vs + (tid + 256 * j) * 4) = vv;
    }
    __syncthreads();

    const int warp = tid >> 5, lane = tid & 31;
    const int s = blockIdx.x * 8 + warp;
    const float4* xp = (const float4*)(x + ((size_t)cap * S_LEN + s) * H_DIM);
    const float4* vp = (const float4*)vs;
    float acc = 0.f;
    #pragma unroll 4
    for (int j = lane; j < H_DIM / 4; j += 32) {
        float4 ev = xp[j], cv = vp[j];
        acc = fmaf(ev.x, cv.x, acc);
        acc = fmaf(ev.y, cv.y, acc);
        acc = fmaf(ev.z, cv.z, acc);
        acc = fmaf(ev.w, cv.w, acc);
    }
    #pragma unroll
    for (int o = 16; o > 0; o >>= 1) acc += __shfl_xor_sync(0xffffffffu, acc, o);
    if (lane == 0) g_b[cap * S_LEN + s] += acc;
}

// ============================================================================
// kernel_launch
// ============================================================================
extern "C" void kernel_launch(void* const* d_in, const int* in_sizes, int n_in,
                              void* d_out, int out_size) {
    const float* x = (const float*)d_in[0];   // [64,128,2048] fp32
    const float* W = (const float*)d_in[1];   // [2048,2048] fp32
    float* out = (float*)d_out;               // [64,2048] fp32 — holds c

    float* u_ptr;
    cudaGetSymbolAddress((void**)&u_ptr, g_u);

    const dim3 gemm_grid(H_DIM / 64, KSPLIT);

    zero_b_kernel<<<8, 1024>>>();

    for (int it = 0; it < 3; ++it) {
        u_kernel<<<dim3(H_DIM / 256, C_CAPS), 256>>>(x);
        gemm_mma_kernel<false><<<gemm_grid, 128>>>(u_ptr, W);        // c = u @ W
        reduce_c_norm_kernel<<<dim3(16, C_CAPS), 128>>>(out);
        squash_scale_kernel<<<C_CAPS, 256>>>(out);
        if (it < 2) {
            gemm_mma_kernel<true><<<gemm_grid, 128>>>(out, W);       // v = c @ W^T
            reduce_v_kernel<<<C_CAPS * H_DIM / 256, 256>>>();
            b_update_kernel<<<dim3(S_LEN / 8, C_CAPS), 256>>>(x);
        }
    }
}